// round 1
// baseline (speedup 1.0000x reference)
#include <cuda_runtime.h>
#include <cstdint>

#define N_PTS   32768
#define DIM     256
#define KCODES  8192
#define HW      1024
#define CHANS   256
#define BATCH   32
#define TILE_M  128
#define TILE_N  128
#define DCHUNK  64
#define NCHUNKS (KCODES / TILE_N)          // 64
#define NSTEPS  (NCHUNKS * (DIM / DCHUNK)) // 256
#define ZQ_ELEMS (BATCH * CHANS * HW)      // 8388608
#define ES_ELEMS (DCHUNK * TILE_N)         // 8192 floats per buffer
#define SMEM_FLOATS (DIM * TILE_M + 2 * ES_ELEMS)
#define SMEM_BYTES  (SMEM_FLOATS * 4)      // 192 KB

// ---- device scratch (no allocations allowed) ----
__device__ float g_eT[DIM * KCODES];   // embedding transposed [d][k], 8 MB
__device__ float g_enorm[KCODES];      // ||e_k||^2
__device__ int   g_idx[N_PTS];         // argmin indices
__device__ float g_acc;                // sum of (z_q - z)^2

// ---------------- small helpers ----------------
__device__ __forceinline__ unsigned long long fma2(unsigned long long a,
                                                   unsigned long long b,
                                                   unsigned long long c) {
    unsigned long long d;
    asm("fma.rn.f32x2 %0, %1, %2, %3;" : "=l"(d) : "l"(a), "l"(b), "l"(c));
    return d;
}
__device__ __forceinline__ unsigned long long dup2(float x) {
    unsigned long long d;
    unsigned int xu = __float_as_uint(x);
    asm("mov.b64 %0, {%1, %1};" : "=l"(d) : "r"(xu));
    return d;
}
__device__ __forceinline__ float2 unpack2(unsigned long long v) {
    unsigned int lo, hi;
    asm("mov.b64 {%0, %1}, %2;" : "=r"(lo), "=r"(hi) : "l"(v));
    float2 r;
    r.x = __uint_as_float(lo);
    r.y = __uint_as_float(hi);
    return r;
}
__device__ __forceinline__ void cpasync16(void* dst_smem, const void* src) {
    uint32_t d = (uint32_t)__cvta_generic_to_shared(dst_smem);
    asm volatile("cp.async.cg.shared.global [%0], [%1], 16;\n" :: "r"(d), "l"(src));
}
#define CP_COMMIT() asm volatile("cp.async.commit_group;\n")
#define CP_WAIT0()  asm volatile("cp.async.wait_group 0;\n")

// ---------------- kernel 1: transpose embedding ----------------
// g_eT[d][k] = e[k][d]
__global__ void transpose_e_kernel(const float* __restrict__ e) {
    __shared__ float tile[32][33];
    int k0 = blockIdx.x * 32;
    int d0 = blockIdx.y * 32;
    int tx = threadIdx.x, ty = threadIdx.y;
    #pragma unroll
    for (int i = ty; i < 32; i += 8)
        tile[i][tx] = e[(size_t)(k0 + i) * DIM + d0 + tx];
    __syncthreads();
    #pragma unroll
    for (int i = ty; i < 32; i += 8)
        g_eT[(size_t)(d0 + i) * KCODES + k0 + tx] = tile[tx][i];
}

// ---------------- kernel 2: codebook row norms (+ zero accumulator) ----------------
__global__ void enorm_kernel(const float* __restrict__ e) {
    int k = blockIdx.x * blockDim.x + threadIdx.x;
    if (k == 0) g_acc = 0.0f;
    if (k >= KCODES) return;
    const float* row = e + (size_t)k * DIM;
    float s = 0.0f;
    #pragma unroll 8
    for (int c = 0; c < DIM; ++c)
        s = __fadd_rn(s, __fmul_rn(row[c], row[c]));
    g_enorm[k] = s;
}

// ---------------- kernel 3: GEMM + fused argmin ----------------
__device__ __forceinline__ void prefetch_es(float* esb, int step) {
    int cc = step >> 2;         // code chunk
    int dc = step & 3;          // d chunk
    const float* src = g_eT + (size_t)(dc * DCHUNK) * KCODES + cc * TILE_N;
    int tid = threadIdx.x;
    #pragma unroll
    for (int j = 0; j < 8; ++j) {
        int i  = tid + j * 256;
        int r  = i >> 5;              // 0..63 (d within chunk)
        int c4 = (i & 31) << 2;       // float4 column within 128 codes
        cpasync16(esb + r * TILE_N + c4, src + (size_t)r * KCODES + c4);
    }
    CP_COMMIT();
}

__global__ void __launch_bounds__(256, 1)
vq_gemm_argmin(const float* __restrict__ z) {
    extern __shared__ float sm[];
    float* zs = sm;                         // [DIM][TILE_M]
    float* es = sm + DIM * TILE_M;          // [2][DCHUNK][TILE_N]
    __shared__ float szs[TILE_M];           // ||z_p||^2 per point

    const int tid  = threadIdx.x;
    const int tile = blockIdx.x;            // 0..255
    const int n0   = tile * TILE_M;
    const int b    = n0 / HW;               // TILE_M divides HW, no straddle
    const int hw0  = n0 % HW;
    const float* zb = z + (size_t)b * CHANS * HW + hw0;  // zb[c*HW + p]

    // kick off first embedding chunk ASAP (overlaps with z-tile load)
    prefetch_es(es, 0);

    // load z tile into smem as [c][p] (global is p-contiguous -> coalesced)
    #pragma unroll
    for (int j = 0; j < 32; ++j) {
        int i  = tid + j * 256;             // 0 .. 8191 float4 slots
        int c  = i >> 5;                    // 0..255
        int p4 = (i & 31) << 2;             // 0..124
        float4 v = *(const float4*)(zb + (size_t)c * HW + p4);
        *(float4*)(zs + c * TILE_M + p4) = v;
    }
    __syncthreads();

    // per-point ||z||^2 (sequential fp32 like the reference's row-sum)
    if (tid < TILE_M) {
        float s = 0.0f;
        #pragma unroll 8
        for (int c = 0; c < DIM; ++c) {
            float v = zs[c * TILE_M + tid];
            s = __fadd_rn(s, __fmul_rn(v, v));
        }
        szs[tid] = s;
    }

    const int tx = tid & 15;        // code sub-tile (8 codes)
    const int ty = tid >> 4;        // point sub-tile (8 points)
    const int p0 = ty * 8;

    float best[8];
    int   bidx[8];
    #pragma unroll
    for (int i = 0; i < 8; ++i) { best[i] = 3.4e38f; bidx[i] = 0x7fffffff; }

    unsigned long long acc[4][8];   // f32x2 accumulators: 4 point-pairs x 8 codes

    for (int cc = 0; cc < NCHUNKS; ++cc) {
        #pragma unroll
        for (int ip = 0; ip < 4; ++ip)
            #pragma unroll
            for (int j = 0; j < 8; ++j)
                acc[ip][j] = 0ULL;

        for (int dc = 0; dc < 4; ++dc) {
            const int s = cc * 4 + dc;
            CP_WAIT0();
            __syncthreads();
            if (s + 1 < NSTEPS)
                prefetch_es(es + ((s + 1) & 1) * ES_ELEMS, s + 1);

            const float* zbase = zs + dc * DCHUNK * TILE_M;
            const float* ebase = es + (s & 1) * ES_ELEMS;

            #pragma unroll 8
            for (int kk = 0; kk < DCHUNK; ++kk) {
                const float* zr = zbase + kk * TILE_M + p0;
                const float* er = ebase + kk * TILE_N + tx * 8;
                ulonglong2 zA = *(const ulonglong2*)(zr);      // points p0..p0+3
                ulonglong2 zB = *(const ulonglong2*)(zr + 4);  // points p0+4..p0+7
                float4 eA = *(const float4*)(er);
                float4 eB = *(const float4*)(er + 4);
                unsigned long long e0 = dup2(eA.x), e1 = dup2(eA.y);
                unsigned long long e2 = dup2(eA.z), e3 = dup2(eA.w);
                unsigned long long e4 = dup2(eB.x), e5 = dup2(eB.y);
                unsigned long long e6 = dup2(eB.z), e7 = dup2(eB.w);
                unsigned long long zp[4] = { zA.x, zA.y, zB.x, zB.y };
                #pragma unroll
                for (int ip = 0; ip < 4; ++ip) {
                    acc[ip][0] = fma2(zp[ip], e0, acc[ip][0]);
                    acc[ip][1] = fma2(zp[ip], e1, acc[ip][1]);
                    acc[ip][2] = fma2(zp[ip], e2, acc[ip][2]);
                    acc[ip][3] = fma2(zp[ip], e3, acc[ip][3]);
                    acc[ip][4] = fma2(zp[ip], e4, acc[ip][4]);
                    acc[ip][5] = fma2(zp[ip], e5, acc[ip][5]);
                    acc[ip][6] = fma2(zp[ip], e6, acc[ip][6]);
                    acc[ip][7] = fma2(zp[ip], e7, acc[ip][7]);
                }
            }
        }

        // epilogue: distances for this 128-code chunk, mimic reference rounding:
        // d = fp32( fp32(sumz + sume) + fp32(-2*dot) )
        const int cbase = cc * TILE_N + tx * 8;
        #pragma unroll
        for (int ip = 0; ip < 4; ++ip) {
            float sz0 = szs[p0 + 2 * ip];
            float sz1 = szs[p0 + 2 * ip + 1];
            #pragma unroll
            for (int j = 0; j < 8; ++j) {
                float2 dot = unpack2(acc[ip][j]);
                float en = g_enorm[cbase + j];
                float d0 = __fadd_rn(__fadd_rn(sz0, en), __fmul_rn(dot.x, -2.0f));
                float d1 = __fadd_rn(__fadd_rn(sz1, en), __fmul_rn(dot.y, -2.0f));
                int ci = cbase + j;
                if (d0 < best[2 * ip])     { best[2 * ip]     = d0; bidx[2 * ip]     = ci; }
                if (d1 < best[2 * ip + 1]) { best[2 * ip + 1] = d1; bidx[2 * ip + 1] = ci; }
            }
        }
    }

    // cross-thread reduction per point (16 tx lanes per point), lowest-index ties
    __syncthreads();
    float* rv = es;                          // reuse es as scratch [16][TILE_M]
    int*   ri = (int*)(es + 16 * TILE_M);
    #pragma unroll
    for (int i = 0; i < 8; ++i) {
        rv[tx * TILE_M + p0 + i] = best[i];
        ri[tx * TILE_M + p0 + i] = bidx[i];
    }
    __syncthreads();
    if (tid < TILE_M) {
        float bv = rv[tid];
        int   bi = ri[tid];
        #pragma unroll
        for (int t = 1; t < 16; ++t) {
            float v = rv[t * TILE_M + tid];
            int   ii = ri[t * TILE_M + tid];
            if (v < bv || (v == bv && ii < bi)) { bv = v; bi = ii; }
        }
        g_idx[n0 + tid] = bi;
    }
}

// ---------------- kernel 4: write z_q (straight-through), accumulate MSE ----------------
__global__ void write_out_kernel(const float* __restrict__ z,
                                 const float* __restrict__ e,
                                 float* __restrict__ out, int out_size) {
    float local = 0.0f;
    int stride = gridDim.x * blockDim.x;
    for (int i = blockIdx.x * blockDim.x + threadIdx.x; i < ZQ_ELEMS; i += stride) {
        int hw = i & (HW - 1);
        int c  = (i >> 10) & (CHANS - 1);
        int b  = i >> 18;
        int n  = (b << 10) | hw;
        int idx = g_idx[n];
        float zv = z[i];
        float q  = e[(size_t)idx * DIM + c];
        float dq = __fsub_rn(q, zv);          // (z_q - z), fp32
        if (i < out_size) out[i] = __fadd_rn(zv, dq);  // z + (z_q - z), like the reference STE
        local = __fadd_rn(local, __fmul_rn(dq, dq));
    }
    // block reduction
    #pragma unroll
    for (int o = 16; o > 0; o >>= 1)
        local += __shfl_xor_sync(0xffffffffu, local, o);
    __shared__ float ws[8];
    int lane = threadIdx.x & 31, wid = threadIdx.x >> 5;
    if (lane == 0) ws[wid] = local;
    __syncthreads();
    if (wid == 0) {
        float v = (lane < 8) ? ws[lane] : 0.0f;
        #pragma unroll
        for (int o = 4; o > 0; o >>= 1)
            v += __shfl_xor_sync(0xffffffffu, v, o);
        if (lane == 0) atomicAdd(&g_acc, v);
    }
}

// ---------------- kernel 5: scalars + indices ----------------
__global__ void finalize_kernel(float* __restrict__ out, int out_size) {
    int t = blockIdx.x * blockDim.x + threadIdx.x;
    if (t < N_PTS) {
        int o = ZQ_ELEMS + 3 + t;
        if (o < out_size) out[o] = (float)g_idx[t];
    }
    if (t == 0) {
        float mse  = g_acc * (1.0f / (float)ZQ_ELEMS);   // /2^23: exact
        float comm = 0.25f * mse;
        float loss = __fadd_rn(comm, mse);
        if (ZQ_ELEMS + 0 < out_size) out[ZQ_ELEMS + 0] = loss;
        if (ZQ_ELEMS + 1 < out_size) out[ZQ_ELEMS + 1] = comm;
        if (ZQ_ELEMS + 2 < out_size) out[ZQ_ELEMS + 2] = mse;
    }
}

// ---------------- launch ----------------
extern "C" void kernel_launch(void* const* d_in, const int* in_sizes, int n_in,
                              void* d_out, int out_size) {
    const float* z = (const float*)d_in[0];
    const float* e = (const float*)d_in[1];
    float* out = (float*)d_out;

    cudaFuncSetAttribute(vq_gemm_argmin,
                         cudaFuncAttributeMaxDynamicSharedMemorySize, SMEM_BYTES);

    transpose_e_kernel<<<dim3(KCODES / 32, DIM / 32), dim3(32, 8)>>>(e);
    enorm_kernel<<<KCODES / 256, 256>>>(e);
    vq_gemm_argmin<<<N_PTS / TILE_M, 256, SMEM_BYTES>>>(z);
    write_out_kernel<<<4096, 256>>>(z, e, out, out_size);
    finalize_kernel<<<(N_PTS + 255) / 256, 256>>>(out, out_size);
}

// round 2
// speedup vs baseline: 1.0004x; 1.0004x over previous
#include <cuda_runtime.h>
#include <cstdint>

#define N_PTS   32768
#define DIM     256
#define KCODES  8192
#define HW      1024
#define CHANS   256
#define BATCH   32
#define TILE_M  128
#define TILE_N  128
#define DCHUNK  64
#define NCHUNKS (KCODES / TILE_N)          // 64
#define NSTEPS  (NCHUNKS * (DIM / DCHUNK)) // 256
#define ZQ_ELEMS (BATCH * CHANS * HW)      // 8388608
#define ES_ELEMS (DCHUNK * TILE_N)         // 8192 floats per buffer
#define SMEM_FLOATS (DIM * TILE_M + 2 * ES_ELEMS)
#define SMEM_BYTES  (SMEM_FLOATS * 4)      // 192 KB

// ---- device scratch (no allocations allowed) ----
__device__ float g_eT[DIM * KCODES];   // embedding transposed [d][k], 8 MB
__device__ float g_enorm[KCODES];      // ||e_k||^2
__device__ int   g_idx[N_PTS];         // argmin indices
__device__ float g_acc;                // sum of (z_q - z)^2

// ---------------- small helpers ----------------
__device__ __forceinline__ unsigned long long fma2(unsigned long long a,
                                                   unsigned long long b,
                                                   unsigned long long c) {
    unsigned long long d;
    asm("fma.rn.f32x2 %0, %1, %2, %3;" : "=l"(d) : "l"(a), "l"(b), "l"(c));
    return d;
}
__device__ __forceinline__ unsigned long long dup2(float x) {
    unsigned long long d;
    unsigned int xu = __float_as_uint(x);
    asm("mov.b64 %0, {%1, %1};" : "=l"(d) : "r"(xu));
    return d;
}
__device__ __forceinline__ float2 unpack2(unsigned long long v) {
    unsigned int lo, hi;
    asm("mov.b64 {%0, %1}, %2;" : "=r"(lo), "=r"(hi) : "l"(v));
    float2 r;
    r.x = __uint_as_float(lo);
    r.y = __uint_as_float(hi);
    return r;
}
__device__ __forceinline__ void cpasync16(void* dst_smem, const void* src) {
    uint32_t d = (uint32_t)__cvta_generic_to_shared(dst_smem);
    asm volatile("cp.async.cg.shared.global [%0], [%1], 16;\n" :: "r"(d), "l"(src));
}
#define CP_COMMIT() asm volatile("cp.async.commit_group;\n")
#define CP_WAIT0()  asm volatile("cp.async.wait_group 0;\n")

// ---------------- kernel 1: transpose embedding ----------------
// g_eT[d][k] = e[k][d]
__global__ void transpose_e_kernel(const float* __restrict__ e) {
    __shared__ float tile[32][33];
    int k0 = blockIdx.x * 32;
    int d0 = blockIdx.y * 32;
    int tx = threadIdx.x, ty = threadIdx.y;
    #pragma unroll
    for (int i = ty; i < 32; i += 8)
        tile[i][tx] = e[(size_t)(k0 + i) * DIM + d0 + tx];
    __syncthreads();
    #pragma unroll
    for (int i = ty; i < 32; i += 8)
        g_eT[(size_t)(d0 + i) * KCODES + k0 + tx] = tile[tx][i];
}

// ---------------- kernel 2: codebook row norms (+ zero accumulator) ----------------
__global__ void enorm_kernel(const float* __restrict__ e) {
    int k = blockIdx.x * blockDim.x + threadIdx.x;
    if (k == 0) g_acc = 0.0f;
    if (k >= KCODES) return;
    const float* row = e + (size_t)k * DIM;
    float s = 0.0f;
    #pragma unroll 8
    for (int c = 0; c < DIM; ++c)
        s = __fadd_rn(s, __fmul_rn(row[c], row[c]));
    g_enorm[k] = s;
}

// ---------------- kernel 3: GEMM + fused argmin ----------------
__device__ __forceinline__ void prefetch_es(float* esb, int step) {
    int cc = step >> 2;         // code chunk
    int dc = step & 3;          // d chunk
    const float* src = g_eT + (size_t)(dc * DCHUNK) * KCODES + cc * TILE_N;
    int tid = threadIdx.x;
    #pragma unroll
    for (int j = 0; j < 8; ++j) {
        int i  = tid + j * 256;
        int r  = i >> 5;              // 0..63 (d within chunk)
        int c4 = (i & 31) << 2;       // float4 column within 128 codes
        cpasync16(esb + r * TILE_N + c4, src + (size_t)r * KCODES + c4);
    }
    CP_COMMIT();
}

__global__ void __launch_bounds__(256, 1)
vq_gemm_argmin(const float* __restrict__ z) {
    extern __shared__ float sm[];
    float* zs = sm;                         // [DIM][TILE_M]
    float* es = sm + DIM * TILE_M;          // [2][DCHUNK][TILE_N]
    __shared__ float szs[TILE_M];           // ||z_p||^2 per point

    const int tid  = threadIdx.x;
    const int tile = blockIdx.x;            // 0..255
    const int n0   = tile * TILE_M;
    const int b    = n0 / HW;               // TILE_M divides HW, no straddle
    const int hw0  = n0 % HW;
    const float* zb = z + (size_t)b * CHANS * HW + hw0;  // zb[c*HW + p]

    // kick off first embedding chunk ASAP (overlaps with z-tile load)
    prefetch_es(es, 0);

    // load z tile into smem as [c][p] (global is p-contiguous -> coalesced)
    #pragma unroll
    for (int j = 0; j < 32; ++j) {
        int i  = tid + j * 256;             // 0 .. 8191 float4 slots
        int c  = i >> 5;                    // 0..255
        int p4 = (i & 31) << 2;             // 0..124
        float4 v = *(const float4*)(zb + (size_t)c * HW + p4);
        *(float4*)(zs + c * TILE_M + p4) = v;
    }
    __syncthreads();

    // per-point ||z||^2 (sequential fp32 like the reference's row-sum)
    if (tid < TILE_M) {
        float s = 0.0f;
        #pragma unroll 8
        for (int c = 0; c < DIM; ++c) {
            float v = zs[c * TILE_M + tid];
            s = __fadd_rn(s, __fmul_rn(v, v));
        }
        szs[tid] = s;
    }

    const int tx = tid & 15;        // code sub-tile (8 codes)
    const int ty = tid >> 4;        // point sub-tile (8 points)
    const int p0 = ty * 8;

    float best[8];
    int   bidx[8];
    #pragma unroll
    for (int i = 0; i < 8; ++i) { best[i] = 3.4e38f; bidx[i] = 0x7fffffff; }

    unsigned long long acc[4][8];   // f32x2 accumulators: 4 point-pairs x 8 codes

    for (int cc = 0; cc < NCHUNKS; ++cc) {
        #pragma unroll
        for (int ip = 0; ip < 4; ++ip)
            #pragma unroll
            for (int j = 0; j < 8; ++j)
                acc[ip][j] = 0ULL;

        for (int dc = 0; dc < 4; ++dc) {
            const int s = cc * 4 + dc;
            CP_WAIT0();
            __syncthreads();
            if (s + 1 < NSTEPS)
                prefetch_es(es + ((s + 1) & 1) * ES_ELEMS, s + 1);

            const float* zbase = zs + dc * DCHUNK * TILE_M;
            const float* ebase = es + (s & 1) * ES_ELEMS;

            #pragma unroll 8
            for (int kk = 0; kk < DCHUNK; ++kk) {
                const float* zr = zbase + kk * TILE_M + p0;
                const float* er = ebase + kk * TILE_N + tx * 8;
                ulonglong2 zA = *(const ulonglong2*)(zr);      // points p0..p0+3
                ulonglong2 zB = *(const ulonglong2*)(zr + 4);  // points p0+4..p0+7
                float4 eA = *(const float4*)(er);
                float4 eB = *(const float4*)(er + 4);
                unsigned long long e0 = dup2(eA.x), e1 = dup2(eA.y);
                unsigned long long e2 = dup2(eA.z), e3 = dup2(eA.w);
                unsigned long long e4 = dup2(eB.x), e5 = dup2(eB.y);
                unsigned long long e6 = dup2(eB.z), e7 = dup2(eB.w);
                unsigned long long zp[4] = { zA.x, zA.y, zB.x, zB.y };
                #pragma unroll
                for (int ip = 0; ip < 4; ++ip) {
                    acc[ip][0] = fma2(zp[ip], e0, acc[ip][0]);
                    acc[ip][1] = fma2(zp[ip], e1, acc[ip][1]);
                    acc[ip][2] = fma2(zp[ip], e2, acc[ip][2]);
                    acc[ip][3] = fma2(zp[ip], e3, acc[ip][3]);
                    acc[ip][4] = fma2(zp[ip], e4, acc[ip][4]);
                    acc[ip][5] = fma2(zp[ip], e5, acc[ip][5]);
                    acc[ip][6] = fma2(zp[ip], e6, acc[ip][6]);
                    acc[ip][7] = fma2(zp[ip], e7, acc[ip][7]);
                }
            }
        }

        // epilogue: distances for this 128-code chunk, mimic reference rounding:
        // d = fp32( fp32(sumz + sume) + fp32(-2*dot) )
        const int cbase = cc * TILE_N + tx * 8;
        #pragma unroll
        for (int ip = 0; ip < 4; ++ip) {
            float sz0 = szs[p0 + 2 * ip];
            float sz1 = szs[p0 + 2 * ip + 1];
            #pragma unroll
            for (int j = 0; j < 8; ++j) {
                float2 dot = unpack2(acc[ip][j]);
                float en = g_enorm[cbase + j];
                float d0 = __fadd_rn(__fadd_rn(sz0, en), __fmul_rn(dot.x, -2.0f));
                float d1 = __fadd_rn(__fadd_rn(sz1, en), __fmul_rn(dot.y, -2.0f));
                int ci = cbase + j;
                if (d0 < best[2 * ip])     { best[2 * ip]     = d0; bidx[2 * ip]     = ci; }
                if (d1 < best[2 * ip + 1]) { best[2 * ip + 1] = d1; bidx[2 * ip + 1] = ci; }
            }
        }
    }

    // cross-thread reduction per point (16 tx lanes per point), lowest-index ties
    __syncthreads();
    float* rv = es;                          // reuse es as scratch [16][TILE_M]
    int*   ri = (int*)(es + 16 * TILE_M);
    #pragma unroll
    for (int i = 0; i < 8; ++i) {
        rv[tx * TILE_M + p0 + i] = best[i];
        ri[tx * TILE_M + p0 + i] = bidx[i];
    }
    __syncthreads();
    if (tid < TILE_M) {
        float bv = rv[tid];
        int   bi = ri[tid];
        #pragma unroll
        for (int t = 1; t < 16; ++t) {
            float v = rv[t * TILE_M + tid];
            int   ii = ri[t * TILE_M + tid];
            if (v < bv || (v == bv && ii < bi)) { bv = v; bi = ii; }
        }
        g_idx[n0 + tid] = bi;
    }
}

// ---------------- kernel 4: write z_q (straight-through), accumulate MSE ----------------
__global__ void write_out_kernel(const float* __restrict__ z,
                                 const float* __restrict__ e,
                                 float* __restrict__ out, int out_size) {
    float local = 0.0f;
    int stride = gridDim.x * blockDim.x;
    for (int i = blockIdx.x * blockDim.x + threadIdx.x; i < ZQ_ELEMS; i += stride) {
        int hw = i & (HW - 1);
        int c  = (i >> 10) & (CHANS - 1);
        int b  = i >> 18;
        int n  = (b << 10) | hw;
        int idx = g_idx[n];
        float zv = z[i];
        float q  = e[(size_t)idx * DIM + c];
        float dq = __fsub_rn(q, zv);          // (z_q - z), fp32
        if (i < out_size) out[i] = __fadd_rn(zv, dq);  // z + (z_q - z), like the reference STE
        local = __fadd_rn(local, __fmul_rn(dq, dq));
    }
    // block reduction
    #pragma unroll
    for (int o = 16; o > 0; o >>= 1)
        local += __shfl_xor_sync(0xffffffffu, local, o);
    __shared__ float ws[8];
    int lane = threadIdx.x & 31, wid = threadIdx.x >> 5;
    if (lane == 0) ws[wid] = local;
    __syncthreads();
    if (wid == 0) {
        float v = (lane < 8) ? ws[lane] : 0.0f;
        #pragma unroll
        for (int o = 4; o > 0; o >>= 1)
            v += __shfl_xor_sync(0xffffffffu, v, o);
        if (lane == 0) atomicAdd(&g_acc, v);
    }
}

// ---------------- kernel 5: scalars + indices ----------------
__global__ void finalize_kernel(float* __restrict__ out, int out_size) {
    int t = blockIdx.x * blockDim.x + threadIdx.x;
    if (t < N_PTS) {
        int o = ZQ_ELEMS + 3 + t;
        if (o < out_size) out[o] = (float)g_idx[t];
    }
    if (t == 0) {
        float mse  = g_acc * (1.0f / (float)ZQ_ELEMS);   // /2^23: exact
        float comm = 0.25f * mse;
        float loss = __fadd_rn(comm, mse);
        if (ZQ_ELEMS + 0 < out_size) out[ZQ_ELEMS + 0] = loss;
        if (ZQ_ELEMS + 1 < out_size) out[ZQ_ELEMS + 1] = comm;
        if (ZQ_ELEMS + 2 < out_size) out[ZQ_ELEMS + 2] = mse;
    }
}

// ---------------- launch ----------------
extern "C" void kernel_launch(void* const* d_in, const int* in_sizes, int n_in,
                              void* d_out, int out_size) {
    const float* z = (const float*)d_in[0];
    const float* e = (const float*)d_in[1];
    float* out = (float*)d_out;

    cudaFuncSetAttribute(vq_gemm_argmin,
                         cudaFuncAttributeMaxDynamicSharedMemorySize, SMEM_BYTES);

    transpose_e_kernel<<<dim3(KCODES / 32, DIM / 32), dim3(32, 8)>>>(e);
    enorm_kernel<<<KCODES / 256, 256>>>(e);
    vq_gemm_argmin<<<N_PTS / TILE_M, 256, SMEM_BYTES>>>(z);
    write_out_kernel<<<4096, 256>>>(z, e, out, out_size);
    finalize_kernel<<<(N_PTS + 255) / 256, 256>>>(out, out_size);
}

// round 4
// speedup vs baseline: 2.7053x; 2.7043x over previous
#include <cuda_runtime.h>
#include <cuda_fp16.h>
#include <cstdint>

#define N_PTS    32768
#define DIM      256
#define KCODES   8192
#define HW       1024
#define CHANS    256
#define ZQ_ELEMS (32 * 256 * 1024)

#define TM       128
#define NTILES   256
#define SB_STAGE 16384
#define NSTAGES  4
#define SA_BYTES 131072
#define SMEM_MAIN (SA_BYTES + NSTAGES * SB_STAGE)   // 196608

__device__ uint4 g_A4[NTILES * 8192];          // 32MB pre-swizzled z hi/lo fp16
__device__ uint4 g_B4[64 * 8 * 1024];          // 8MB  pre-swizzled e hi/lo fp16
__device__ float g_enorm[KCODES];
__device__ float g_sz[N_PTS];
__device__ unsigned long long g_best[N_PTS];
__device__ int   g_idx[N_PTS];
__device__ float g_acc;

__device__ __forceinline__ uint32_t smem_u32(const void* p) {
    return (uint32_t)__cvta_generic_to_shared(p);
}
__device__ __forceinline__ void cpasync16(void* dst, const void* src) {
    asm volatile("cp.async.cg.shared.global [%0], [%1], 16;\n"
                 :: "r"(smem_u32(dst)), "l"(src));
}
#define CP_COMMIT() asm volatile("cp.async.commit_group;\n" ::: "memory")
#define CP_WAIT2()  asm volatile("cp.async.wait_group 2;\n" ::: "memory")

__device__ __forceinline__ void ldsm4(uint32_t* r, uint32_t addr) {
    asm volatile("ldmatrix.sync.aligned.m8n8.x4.shared.b16 {%0,%1,%2,%3}, [%4];"
                 : "=r"(r[0]), "=r"(r[1]), "=r"(r[2]), "=r"(r[3]) : "r"(addr));
}
__device__ __forceinline__ void mma16816(float* d, const uint32_t* a, const uint32_t* b) {
    asm volatile("mma.sync.aligned.m16n8k16.row.col.f32.f16.f16.f32 "
                 "{%0,%1,%2,%3}, {%4,%5,%6,%7}, {%8,%9}, {%0,%1,%2,%3};"
                 : "+f"(d[0]), "+f"(d[1]), "+f"(d[2]), "+f"(d[3])
                 : "r"(a[0]), "r"(a[1]), "r"(a[2]), "r"(a[3]), "r"(b[0]), "r"(b[1]));
}
__device__ __forceinline__ uint32_t pack2h(__half a, __half b) {
    return (uint32_t)__half_as_ushort(a) | ((uint32_t)__half_as_ushort(b) << 16);
}

// ---------- prep A: per-tile swizzled fp16 hi/lo images ----------
__global__ void prep_z_kernel(const float* __restrict__ z) {
    int t = blockIdx.x, tid = threadIdx.x;
    int n0 = t * TM, b = n0 >> 10, hw0 = n0 & 1023;
    const float* zb = z + (size_t)b * CHANS * HW + hw0;
    #pragma unroll
    for (int m = 0; m < 16; ++m) {
        int u = tid + m * 256;              // 0..4095
        int p = u & 127, kc = u >> 7;       // kc 0..31
        float v[8];
        #pragma unroll
        for (int j = 0; j < 8; ++j)
            v[j] = zb[(size_t)(kc * 8 + j) * HW + p];
        __half h[8], l[8];
        #pragma unroll
        for (int j = 0; j < 8; ++j) {
            h[j] = __float2half_rn(v[j]);
            l[j] = __float2half_rn(__fsub_rn(v[j], __half2float(h[j])));
        }
        uint4 hx = make_uint4(pack2h(h[0],h[1]), pack2h(h[2],h[3]),
                              pack2h(h[4],h[5]), pack2h(h[6],h[7]));
        uint4 lx = make_uint4(pack2h(l[0],l[1]), pack2h(l[2],l[3]),
                              pack2h(l[4],l[5]), pack2h(l[6],l[7]));
        int slot = p * 32 + ((kc & 24) | ((kc ^ (p & 7)) & 7));
        g_A4[(size_t)t * 8192 + slot]        = hx;
        g_A4[(size_t)t * 8192 + 4096 + slot] = lx;
    }
}

// ---------- prep B: per-chunk 8 swizzled 16KB slabs (4 hi + 4 lo) ----------
__global__ void prep_e_kernel(const float* __restrict__ e) {
    int c = blockIdx.x, tid = threadIdx.x;   // c: code chunk 0..63
    #pragma unroll
    for (int m = 0; m < 32; ++m) {
        int u = tid + m * 256;               // 0..8191
        int s = u >> 10;                     // slab 0..7
        int w = u & 1023;
        int code = w >> 3, kc = w & 7;
        int ch0 = (s & 3) * 64 + kc * 8;
        const float* ep = e + (size_t)(c * 128 + code) * DIM + ch0;
        bool lo = (s >= 4);
        __half h[8];
        #pragma unroll
        for (int j = 0; j < 8; ++j) {
            float ev = ep[j] * 8192.0f;      // exact
            __half hi = __float2half_rn(ev);
            h[j] = lo ? __float2half_rn(__fsub_rn(ev, __half2float(hi))) : hi;
        }
        uint4 x = make_uint4(pack2h(h[0],h[1]), pack2h(h[2],h[3]),
                             pack2h(h[4],h[5]), pack2h(h[6],h[7]));
        int slot = code * 8 + (kc ^ (code & 7));
        g_B4[((size_t)c * 8 + s) * 1024 + slot] = x;
    }
}

__global__ void sz_kernel(const float* __restrict__ z) {
    int p = blockIdx.x * blockDim.x + threadIdx.x;
    if (p >= N_PTS) return;
    int b = p >> 10, hw = p & 1023;
    const float* zp = z + (size_t)b * CHANS * HW + hw;
    float s = 0.0f;
    #pragma unroll 8
    for (int c = 0; c < DIM; ++c) {
        float v = zp[(size_t)c * HW];
        s = __fadd_rn(s, __fmul_rn(v, v));
    }
    g_sz[p] = s;
}

__global__ void enorm_kernel(const float* __restrict__ e) {
    int k = blockIdx.x * blockDim.x + threadIdx.x;
    if (k == 0) g_acc = 0.0f;
    if (k >= KCODES) return;
    const float* row = e + (size_t)k * DIM;
    float s = 0.0f;
    #pragma unroll 8
    for (int c = 0; c < DIM; ++c)
        s = __fadd_rn(s, __fmul_rn(row[c], row[c]));
    g_enorm[k] = s;
}

__global__ void init_best_kernel() {
    int p = blockIdx.x * blockDim.x + threadIdx.x;
    if (p < N_PTS) g_best[p] = 0xFFFFFFFFFFFFFFFFULL;
}

// ---------- main fp16 tensor-core GEMM + fused argmin ----------
__global__ void __launch_bounds__(256, 1) vq_main() {
    extern __shared__ __align__(16) char sm[];
    char* sB = sm + SA_BYTES;
    const uint32_t sAu  = smem_u32(sm);
    const uint32_t sBu  = smem_u32(sB);

    const int tid = threadIdx.x;
    const int wid = tid >> 5, lane = tid & 31;
    const int wm = wid >> 2, wn = wid & 3;
    const int tile = blockIdx.x >> 2, q = blockIdx.x & 3;
    const int n0 = tile * TM;

    // prologue: A (linear copy of pre-swizzled image) + first 3 B slabs
    {
        const uint4* Asrc = g_A4 + (size_t)tile * 8192;
        uint4* Adst = (uint4*)sm;
        #pragma unroll
        for (int m = 0; m < 32; ++m)
            cpasync16(Adst + tid + m * 256, Asrc + tid + m * 256);
        const uint4* B0 = g_B4 + (size_t)(q * 16) * 8 * 1024;
        uint4* bd0 = (uint4*)sB;
        #pragma unroll
        for (int m = 0; m < 4; ++m) cpasync16(bd0 + tid + m * 256, B0 + tid + m * 256);
        CP_COMMIT();
        #pragma unroll
        for (int m = 0; m < 4; ++m) cpasync16(bd0 + 1024 + tid + m * 256, B0 + 1024 + tid + m * 256);
        CP_COMMIT();
        #pragma unroll
        for (int m = 0; m < 4; ++m) cpasync16(bd0 + 2048 + tid + m * 256, B0 + 2048 + tid + m * 256);
        CP_COMMIT();
    }

    // per-thread fixed geometry
    const int lrow = lane >> 2;               // 0..7
    const int lc2  = lane & 3;                // n column pair
    float szr[8];
    #pragma unroll
    for (int i = 0; i < 8; ++i) {
        int mi = i >> 1, h = i & 1;
        szr[i] = g_sz[n0 + wm * 64 + mi * 16 + lrow + h * 8];
    }
    unsigned long long best[8];
    #pragma unroll
    for (int i = 0; i < 8; ++i) best[i] = 0xFFFFFFFFFFFFFFFFULL;

    // A ldmatrix per-lane bases (bytes): p = pbase + (lane&15)
    uint32_t aRow[4];
    int px7;
    {
        int p = (lane & 15);
        #pragma unroll
        for (int mi = 0; mi < 4; ++mi)
            aRow[mi] = (uint32_t)((wm * 64 + mi * 16 + p) * 512);
        px7 = (wm * 64 + p) & 7;              // mi*16 doesn't change low 3 bits
    }
    const int aCadd = (lane >> 4);            // c offset from lane
    // B ldmatrix per-lane fixed parts
    int bCode[2], bKadd = (lane >> 3) & 1;
    bCode[0] = wn * 32 + (lane & 7) + ((lane >> 4) << 3);
    bCode[1] = bCode[0] + 16;

    float acc[4][4][4];

    for (int cg = 0; cg < 16; ++cg) {
        #pragma unroll
        for (int mi = 0; mi < 4; ++mi)
            #pragma unroll
            for (int nj = 0; nj < 4; ++nj)
                #pragma unroll
                for (int r = 0; r < 4; ++r) acc[mi][nj][r] = 0.0f;

        for (int s = 0; s < 8; ++s) {
            const int sidx = cg * 8 + s;
            CP_WAIT2();
            __syncthreads();

            const uint32_t bufb = sBu + (uint32_t)((sidx & 3) * SB_STAGE);
            const int npass = (s < 4) ? 2 : 1;
            const int ak0b = (s & 3) * 64;

            #pragma unroll
            for (int js = 0; js < 4; ++js) {
                const int k0l = js * 16;
                uint32_t b[8];
                {
                    int kc = (k0l >> 3) + bKadd;
                    ldsm4(b,     bufb + (uint32_t)(bCode[0] * 128 + ((kc ^ (bCode[0] & 7)) << 4)));
                    ldsm4(b + 4, bufb + (uint32_t)(bCode[1] * 128 + ((kc ^ (bCode[1] & 7)) << 4)));
                }
                #pragma unroll
                for (int pass = 0; pass < 2; ++pass) {
                    if (pass == 1 && npass == 1) break;
                    const uint32_t term = (npass == 2 && pass == 1) ? (sAu + 65536) : sAu;
                    const int c = ((ak0b + k0l) >> 3) + aCadd;
                    const uint32_t co = (uint32_t)(((c & 24) | ((c ^ px7) & 7)) << 4);
                    uint32_t a[4][4];
                    #pragma unroll
                    for (int mi = 0; mi < 4; ++mi)
                        ldsm4(a[mi], term + aRow[mi] + co);
                    #pragma unroll
                    for (int mi = 0; mi < 4; ++mi) {
                        mma16816(acc[mi][0], a[mi], b);
                        mma16816(acc[mi][1], a[mi], b + 2);
                        mma16816(acc[mi][2], a[mi], b + 4);
                        mma16816(acc[mi][3], a[mi], b + 6);
                    }
                }
            }

            const int nx = sidx + 3;
            if (nx < 128) {
                const uint4* src = g_B4 + ((size_t)(q * 16 + (nx >> 3)) * 8 + (nx & 7)) * 1024;
                uint4* dst = (uint4*)(sB + (nx & 3) * SB_STAGE);
                #pragma unroll
                for (int m = 0; m < 4; ++m)
                    cpasync16(dst + tid + m * 256, src + tid + m * 256);
            }
            CP_COMMIT();
        }

        // epilogue: distances + running u64 min (value, then lowest index)
        const int cbase = q * 2048 + cg * 128 + wn * 32;
        float en[8];
        #pragma unroll
        for (int nj = 0; nj < 4; ++nj) {
            en[nj * 2]     = g_enorm[cbase + nj * 8 + lc2 * 2];
            en[nj * 2 + 1] = g_enorm[cbase + nj * 8 + lc2 * 2 + 1];
        }
        #pragma unroll
        for (int mi = 0; mi < 4; ++mi)
            #pragma unroll
            for (int nj = 0; nj < 4; ++nj)
                #pragma unroll
                for (int r = 0; r < 4; ++r) {
                    int i = mi * 2 + (r >> 1);
                    int j = nj * 2 + (r & 1);
                    float t = __fmul_rn(acc[mi][nj][r], -2.44140625e-4f);  // = -2 * (acc/8192)
                    float d = __fadd_rn(__fadd_rn(szr[i], en[j]), t);
                    unsigned idx = (unsigned)(cbase + nj * 8 + lc2 * 2 + (r & 1));
                    unsigned long long pk =
                        ((unsigned long long)__float_as_uint(d) << 32) | idx;
                    if (pk < best[i]) best[i] = pk;
                }
    }

    // cross-warp reduction (16 threads share each point), then global atomicMin
    __syncthreads();
    unsigned long long* red = (unsigned long long*)sB;   // 16KB scratch
    const int slot = wn * 4 + lc2;
    #pragma unroll
    for (int i = 0; i < 8; ++i) {
        int mi = i >> 1, h = i & 1;
        int p = wm * 64 + mi * 16 + lrow + h * 8;
        red[p * 16 + slot] = best[i];
    }
    __syncthreads();
    if (tid < 128) {
        unsigned long long v = red[tid * 16];
        #pragma unroll
        for (int t = 1; t < 16; ++t) {
            unsigned long long w = red[tid * 16 + t];
            if (w < v) v = w;
        }
        atomicMin(&g_best[n0 + tid], v);
    }
}

__global__ void extract_kernel() {
    int p = blockIdx.x * blockDim.x + threadIdx.x;
    if (p < N_PTS) g_idx[p] = (int)(unsigned)(g_best[p] & 0xFFFFFFFFULL);
}

// ---------- outputs (unchanged from R1, verified) ----------
__global__ void write_out_kernel(const float* __restrict__ z,
                                 const float* __restrict__ e,
                                 float* __restrict__ out, int out_size) {
    float local = 0.0f;
    int stride = gridDim.x * blockDim.x;
    for (int i = blockIdx.x * blockDim.x + threadIdx.x; i < ZQ_ELEMS; i += stride) {
        int hw = i & (HW - 1);
        int c  = (i >> 10) & (CHANS - 1);
        int b  = i >> 18;
        int idx = g_idx[(b << 10) | hw];
        float zv = z[i];
        float dq = __fsub_rn(e[(size_t)idx * DIM + c], zv);
        if (i < out_size) out[i] = __fadd_rn(zv, dq);
        local = __fadd_rn(local, __fmul_rn(dq, dq));
    }
    #pragma unroll
    for (int o = 16; o > 0; o >>= 1) local += __shfl_xor_sync(~0u, local, o);
    __shared__ float ws[8];
    int lane = threadIdx.x & 31, w = threadIdx.x >> 5;
    if (lane == 0) ws[w] = local;
    __syncthreads();
    if (w == 0) {
        float v = (lane < 8) ? ws[lane] : 0.0f;
        #pragma unroll
        for (int o = 4; o > 0; o >>= 1) v += __shfl_xor_sync(~0u, v, o);
        if (lane == 0) atomicAdd(&g_acc, v);
    }
}

__global__ void finalize_kernel(float* __restrict__ out, int out_size) {
    int t = blockIdx.x * blockDim.x + threadIdx.x;
    if (t < N_PTS) {
        int o = ZQ_ELEMS + 3 + t;
        if (o < out_size) out[o] = (float)g_idx[t];
    }
    if (t == 0) {
        float mse  = g_acc * (1.0f / (float)ZQ_ELEMS);
        float comm = 0.25f * mse;
        if (ZQ_ELEMS + 0 < out_size) out[ZQ_ELEMS + 0] = __fadd_rn(comm, mse);
        if (ZQ_ELEMS + 1 < out_size) out[ZQ_ELEMS + 1] = comm;
        if (ZQ_ELEMS + 2 < out_size) out[ZQ_ELEMS + 2] = mse;
    }
}

extern "C" void kernel_launch(void* const* d_in, const int* in_sizes, int n_in,
                              void* d_out, int out_size) {
    const float* z = (const float*)d_in[0];
    const float* e = (const float*)d_in[1];
    float* out = (float*)d_out;
    cudaFuncSetAttribute(vq_main, cudaFuncAttributeMaxDynamicSharedMemorySize, SMEM_MAIN);
    prep_z_kernel<<<NTILES, 256>>>(z);
    prep_e_kernel<<<64, 256>>>(e);
    sz_kernel<<<N_PTS / 256, 256>>>(z);
    enorm_kernel<<<KCODES / 256, 256>>>(e);
    init_best_kernel<<<N_PTS / 256, 256>>>();
    vq_main<<<1024, 256, SMEM_MAIN>>>();
    extract_kernel<<<N_PTS / 256, 256>>>();
    write_out_kernel<<<4096, 256>>>(z, e, out, out_size);
    finalize_kernel<<<(N_PTS + 255) / 256, 256>>>(out, out_size);
}

// round 5
// speedup vs baseline: 3.1971x; 1.1818x over previous
#include <cuda_runtime.h>
#include <cuda_fp16.h>
#include <cstdint>

#define N_PTS    32768
#define DIM      256
#define KCODES   8192
#define HW       1024
#define CHANS    256
#define ZQ_ELEMS (32 * 256 * 1024)

#define TM       128
#define NTILES   256
#define SB_STAGE 16384
#define SA_BYTES 65536
#define SMEM_MAIN (SA_BYTES + 4 * SB_STAGE)   // 131072

typedef unsigned long long u64;

__device__ uint4 g_A4[NTILES * 4096];      // 16MB pre-swizzled z_hi fp16
__device__ uint4 g_B4[64 * 4 * 1024];      // 4MB  pre-swizzled e_hi fp16
__device__ float g_enorm[KCODES];
__device__ float g_sz[N_PTS];
__device__ float g_zT[N_PTS * DIM];        // 32MB contiguous z rows
__device__ u64   g_cand[N_PTS * 128];      // 32MB candidate pool
__device__ int   g_idx[N_PTS];
__device__ float g_acc;

__device__ __forceinline__ uint32_t smem_u32(const void* p) {
    return (uint32_t)__cvta_generic_to_shared(p);
}
__device__ __forceinline__ void cpasync16(void* dst, const void* src) {
    asm volatile("cp.async.cg.shared.global [%0], [%1], 16;\n"
                 :: "r"(smem_u32(dst)), "l"(src));
}
#define CP_COMMIT() asm volatile("cp.async.commit_group;\n" ::: "memory")
#define CP_WAIT2()  asm volatile("cp.async.wait_group 2;\n" ::: "memory")

__device__ __forceinline__ void ldsm4(uint32_t* r, uint32_t addr) {
    asm volatile("ldmatrix.sync.aligned.m8n8.x4.shared.b16 {%0,%1,%2,%3}, [%4];"
                 : "=r"(r[0]), "=r"(r[1]), "=r"(r[2]), "=r"(r[3]) : "r"(addr));
}
__device__ __forceinline__ void mma16816(float* d, const uint32_t* a, const uint32_t* b) {
    asm volatile("mma.sync.aligned.m16n8k16.row.col.f32.f16.f16.f32 "
                 "{%0,%1,%2,%3}, {%4,%5,%6,%7}, {%8,%9}, {%0,%1,%2,%3};"
                 : "+f"(d[0]), "+f"(d[1]), "+f"(d[2]), "+f"(d[3])
                 : "r"(a[0]), "r"(a[1]), "r"(a[2]), "r"(a[3]), "r"(b[0]), "r"(b[1]));
}
__device__ __forceinline__ uint32_t pack2h(__half a, __half b) {
    return (uint32_t)__half_as_ushort(a) | ((uint32_t)__half_as_ushort(b) << 16);
}

// ---------- prep A: per-tile swizzled fp16 z_hi images ----------
__global__ void prep_z_kernel(const float* __restrict__ z) {
    int t = blockIdx.x, tid = threadIdx.x;
    int n0 = t * TM, b = n0 >> 10, hw0 = n0 & 1023;
    const float* zb = z + (size_t)b * CHANS * HW + hw0;
    #pragma unroll
    for (int m = 0; m < 16; ++m) {
        int u = tid + m * 256;              // 0..4095
        int p = u & 127, kc = u >> 7;       // kc 0..31
        __half h[8];
        #pragma unroll
        for (int j = 0; j < 8; ++j)
            h[j] = __float2half_rn(zb[(size_t)(kc * 8 + j) * HW + p]);
        uint4 hx = make_uint4(pack2h(h[0],h[1]), pack2h(h[2],h[3]),
                              pack2h(h[4],h[5]), pack2h(h[6],h[7]));
        int slot = p * 32 + ((kc & 24) | ((kc ^ (p & 7)) & 7));
        g_A4[(size_t)t * 4096 + slot] = hx;
    }
}

// ---------- prep B: per-chunk 4 swizzled 16KB e_hi slabs ----------
__global__ void prep_e_kernel(const float* __restrict__ e) {
    int c = blockIdx.x, tid = threadIdx.x;   // chunk 0..63
    #pragma unroll
    for (int m = 0; m < 16; ++m) {
        int u = tid + m * 256;               // 0..4095
        int s = u >> 10;                     // slab 0..3
        int w = u & 1023;
        int code = w >> 3, kc = w & 7;
        const float* ep = e + (size_t)(c * 128 + code) * DIM + s * 64 + kc * 8;
        __half h[8];
        #pragma unroll
        for (int j = 0; j < 8; ++j)
            h[j] = __float2half_rn(ep[j] * 8192.0f);   // exact scale
        uint4 x = make_uint4(pack2h(h[0],h[1]), pack2h(h[2],h[3]),
                             pack2h(h[4],h[5]), pack2h(h[6],h[7]));
        int slot = code * 8 + (kc ^ (code & 7));
        g_B4[((size_t)c * 4 + s) * 1024 + slot] = x;
    }
}

// ---------- zT + per-point ||z||^2 ----------
__global__ void szT_kernel(const float* __restrict__ z) {
    __shared__ float s_t[256 * 33];
    int blk = blockIdx.x, tid = threadIdx.x;
    int n0 = blk * 32, b = n0 >> 10, hw0 = n0 & 1023;
    const float* zb = z + (size_t)b * CHANS * HW + hw0;
    #pragma unroll
    for (int m = 0; m < 32; ++m) {
        int c = m * 8 + (tid >> 5), p = tid & 31;
        s_t[c * 33 + p] = zb[(size_t)c * HW + p];
    }
    __syncthreads();
    if (tid < 32) {
        float s = 0.0f;
        #pragma unroll 8
        for (int c = 0; c < 256; ++c) {
            float v = s_t[c * 33 + tid];
            s = __fadd_rn(s, __fmul_rn(v, v));
        }
        g_sz[n0 + tid] = s;
    }
    #pragma unroll
    for (int m = 0; m < 8; ++m) {
        int p = tid >> 3, c0 = (tid & 7) * 4 + m * 32;
        float4 v;
        v.x = s_t[(c0    ) * 33 + p]; v.y = s_t[(c0 + 1) * 33 + p];
        v.z = s_t[(c0 + 2) * 33 + p]; v.w = s_t[(c0 + 3) * 33 + p];
        *(float4*)(g_zT + (size_t)(n0 + p) * DIM + c0) = v;
    }
}

// ---------- codebook norms (warp per 4 codes) ----------
__global__ void enorm_kernel(const float* __restrict__ e) {
    int tid = threadIdx.x, lane = tid & 31;
    int gw = blockIdx.x * 8 + (tid >> 5);     // 0..2047
    if (blockIdx.x == 0 && tid == 0) g_acc = 0.0f;
    #pragma unroll
    for (int i = 0; i < 4; ++i) {
        int k = gw * 4 + i;
        const float* row = e + (size_t)k * DIM + lane * 8;
        float s = 0.0f;
        #pragma unroll
        for (int j = 0; j < 8; ++j)
            s = __fadd_rn(s, __fmul_rn(row[j], row[j]));
        #pragma unroll
        for (int o = 16; o > 0; o >>= 1)
            s = __fadd_rn(s, __shfl_xor_sync(~0u, s, o));
        if (lane == 0) g_enorm[k] = s;
    }
}

// ---------- main approximate GEMM (K=256 z_hi*e_hi) + top-2 candidates ----------
__global__ void __launch_bounds__(256, 1) vq_main() {
    extern __shared__ __align__(16) char sm[];
    char* sB = sm + SA_BYTES;
    const uint32_t sAu = smem_u32(sm);
    const uint32_t sBu = smem_u32(sB);

    const int tid = threadIdx.x;
    const int wid = tid >> 5, lane = tid & 31;
    const int wm = wid >> 2, wn = wid & 3;
    const int tile = blockIdx.x >> 2, q = blockIdx.x & 3;
    const int n0 = tile * TM;
    const uint4* Bbase = g_B4 + (size_t)q * 64 * 1024;

    {
        const uint4* Asrc = g_A4 + (size_t)tile * 4096;
        uint4* Adst = (uint4*)sm;
        #pragma unroll
        for (int m = 0; m < 16; ++m)
            cpasync16(Adst + tid + m * 256, Asrc + tid + m * 256);
        uint4* bd = (uint4*)sB;
        #pragma unroll
        for (int m = 0; m < 4; ++m) cpasync16(bd + tid + m * 256, Bbase + tid + m * 256);
        CP_COMMIT();
        #pragma unroll
        for (int m = 0; m < 4; ++m) cpasync16(bd + 1024 + tid + m * 256, Bbase + 1024 + tid + m * 256);
        CP_COMMIT();
        #pragma unroll
        for (int m = 0; m < 4; ++m) cpasync16(bd + 2048 + tid + m * 256, Bbase + 2048 + tid + m * 256);
        CP_COMMIT();
    }

    const int lrow = lane >> 2;
    const int lc2  = lane & 3;
    float szr[8];
    #pragma unroll
    for (int i = 0; i < 8; ++i) {
        int mi = i >> 1, h = i & 1;
        szr[i] = g_sz[n0 + wm * 64 + mi * 16 + lrow + h * 8];
    }
    u64 best1[8], best2[8];
    #pragma unroll
    for (int i = 0; i < 8; ++i) { best1[i] = ~0ULL; best2[i] = ~0ULL; }

    uint32_t aRow[4];
    int px7;
    {
        int p = (lane & 15);
        #pragma unroll
        for (int mi = 0; mi < 4; ++mi)
            aRow[mi] = (uint32_t)((wm * 64 + mi * 16 + p) * 512);
        px7 = (wm * 64 + p) & 7;
    }
    const int aCadd = (lane >> 4);
    int bCode[2], bKadd = (lane >> 3) & 1;
    bCode[0] = wn * 32 + (lane & 7) + ((lane >> 4) << 3);
    bCode[1] = bCode[0] + 16;

    float acc[4][4][4];

    for (int cg = 0; cg < 16; ++cg) {
        #pragma unroll
        for (int mi = 0; mi < 4; ++mi)
            #pragma unroll
            for (int nj = 0; nj < 4; ++nj)
                #pragma unroll
                for (int r = 0; r < 4; ++r) acc[mi][nj][r] = 0.0f;

        for (int s = 0; s < 4; ++s) {
            const int sidx = cg * 4 + s;
            CP_WAIT2();
            __syncthreads();
            const uint32_t bufb = sBu + (uint32_t)((sidx & 3) * SB_STAGE);

            #pragma unroll
            for (int js = 0; js < 4; ++js) {
                uint32_t bfr[8];
                {
                    int kc = js * 2 + bKadd;
                    ldsm4(bfr,     bufb + (uint32_t)(bCode[0] * 128 + ((kc ^ (bCode[0] & 7)) << 4)));
                    ldsm4(bfr + 4, bufb + (uint32_t)(bCode[1] * 128 + ((kc ^ (bCode[1] & 7)) << 4)));
                }
                const int c = s * 8 + js * 2 + aCadd;
                const uint32_t co = (uint32_t)(((c & 24) | ((c ^ px7) & 7)) << 4);
                uint32_t a[4][4];
                #pragma unroll
                for (int mi = 0; mi < 4; ++mi)
                    ldsm4(a[mi], sAu + aRow[mi] + co);
                #pragma unroll
                for (int mi = 0; mi < 4; ++mi) {
                    mma16816(acc[mi][0], a[mi], bfr);
                    mma16816(acc[mi][1], a[mi], bfr + 2);
                    mma16816(acc[mi][2], a[mi], bfr + 4);
                    mma16816(acc[mi][3], a[mi], bfr + 6);
                }
            }

            const int nx = sidx + 3;
            if (nx < 64) {
                const uint4* src = Bbase + (size_t)nx * 1024;
                uint4* dst = (uint4*)(sB + (nx & 3) * SB_STAGE);
                #pragma unroll
                for (int m = 0; m < 4; ++m)
                    cpasync16(dst + tid + m * 256, src + tid + m * 256);
            }
            CP_COMMIT();
        }

        // distances + per-thread top-2 (u64 = (f32 bits << 32) | idx, d > 0)
        const int cbase = q * 2048 + cg * 128 + wn * 32;
        float en[8];
        #pragma unroll
        for (int nj = 0; nj < 4; ++nj) {
            en[nj * 2]     = g_enorm[cbase + nj * 8 + lc2 * 2];
            en[nj * 2 + 1] = g_enorm[cbase + nj * 8 + lc2 * 2 + 1];
        }
        #pragma unroll
        for (int mi = 0; mi < 4; ++mi)
            #pragma unroll
            for (int nj = 0; nj < 4; ++nj)
                #pragma unroll
                for (int r = 0; r < 4; ++r) {
                    int i = mi * 2 + (r >> 1);
                    float t = __fmul_rn(acc[mi][nj][r], -2.44140625e-4f);
                    float d = __fadd_rn(__fadd_rn(szr[i], en[nj * 2 + (r & 1)]), t);
                    unsigned idx = (unsigned)(cbase + nj * 8 + lc2 * 2 + (r & 1));
                    u64 pk = ((u64)__float_as_uint(d) << 32) | idx;
                    if (pk < best1[i]) { best2[i] = best1[i]; best1[i] = pk; }
                    else if (pk < best2[i]) best2[i] = pk;
                }
    }

    // race-free candidate writes: fixed slot per (cta-quarter, thread, rank)
    const int slot = (wn * 4 + lc2) * 2;
    #pragma unroll
    for (int i = 0; i < 8; ++i) {
        int mi = i >> 1, h = i & 1;
        int p = wm * 64 + mi * 16 + lrow + h * 8;
        u64* dst = g_cand + (size_t)(n0 + p) * 128 + q * 32 + slot;
        dst[0] = best1[i];
        dst[1] = best2[i];
    }
}

// ---------- refine: top-8 of 128 candidates, exact fp32 distance ----------
__global__ void refine_kernel(const float* __restrict__ e) {
    int tid = threadIdx.x, lane = tid & 31;
    int p = blockIdx.x * 8 + (tid >> 5);
    u64 cand[4];
    #pragma unroll
    for (int j = 0; j < 4; ++j)
        cand[j] = g_cand[(size_t)p * 128 + lane * 4 + j];
    float sz = g_sz[p];
    const float* zr = g_zT + (size_t)p * DIM + lane * 8;
    float4 za = *(const float4*)zr;
    float4 zb = *(const float4*)(zr + 4);

    u64 bestf = ~0ULL;
    #pragma unroll 1
    for (int r = 0; r < 8; ++r) {
        u64 m = cand[0];
        if (cand[1] < m) m = cand[1];
        if (cand[2] < m) m = cand[2];
        if (cand[3] < m) m = cand[3];
        #pragma unroll
        for (int o = 16; o > 0; o >>= 1) {
            u64 w = __shfl_xor_sync(~0u, m, o);
            if (w < m) m = w;
        }
        #pragma unroll
        for (int j = 0; j < 4; ++j)
            if (cand[j] == m) cand[j] = ~0ULL;
        unsigned k = (unsigned)m;
        const float* er = e + (size_t)k * DIM + lane * 8;
        float4 ea = *(const float4*)er;
        float4 eb = *(const float4*)(er + 4);
        float s = 0.0f;
        s = __fadd_rn(s, __fmul_rn(za.x, ea.x));
        s = __fadd_rn(s, __fmul_rn(za.y, ea.y));
        s = __fadd_rn(s, __fmul_rn(za.z, ea.z));
        s = __fadd_rn(s, __fmul_rn(za.w, ea.w));
        s = __fadd_rn(s, __fmul_rn(zb.x, eb.x));
        s = __fadd_rn(s, __fmul_rn(zb.y, eb.y));
        s = __fadd_rn(s, __fmul_rn(zb.z, eb.z));
        s = __fadd_rn(s, __fmul_rn(zb.w, eb.w));
        #pragma unroll
        for (int o = 16; o > 0; o >>= 1)
            s = __fadd_rn(s, __shfl_xor_sync(~0u, s, o));
        float d = __fadd_rn(__fadd_rn(sz, g_enorm[k]), __fmul_rn(s, -2.0f));
        u64 pk = ((u64)__float_as_uint(d) << 32) | k;
        if (pk < bestf) bestf = pk;
    }
    if (lane == 0) g_idx[p] = (int)(unsigned)bestf;
}

// ---------- outputs ----------
__global__ void write_out_kernel(const float* __restrict__ z,
                                 const float* __restrict__ e,
                                 float* __restrict__ out, int out_size) {
    float local = 0.0f;
    int stride = gridDim.x * blockDim.x;
    for (int i = blockIdx.x * blockDim.x + threadIdx.x; i < ZQ_ELEMS; i += stride) {
        int hw = i & (HW - 1);
        int c  = (i >> 10) & (CHANS - 1);
        int b  = i >> 18;
        int idx = g_idx[(b << 10) | hw];
        float zv = z[i];
        float dq = __fsub_rn(e[(size_t)idx * DIM + c], zv);
        if (i < out_size) out[i] = __fadd_rn(zv, dq);
        local = __fadd_rn(local, __fmul_rn(dq, dq));
    }
    #pragma unroll
    for (int o = 16; o > 0; o >>= 1) local += __shfl_xor_sync(~0u, local, o);
    __shared__ float ws[8];
    int lane = threadIdx.x & 31, w = threadIdx.x >> 5;
    if (lane == 0) ws[w] = local;
    __syncthreads();
    if (w == 0) {
        float v = (lane < 8) ? ws[lane] : 0.0f;
        #pragma unroll
        for (int o = 4; o > 0; o >>= 1) v += __shfl_xor_sync(~0u, v, o);
        if (lane == 0) atomicAdd(&g_acc, v);
    }
}

__global__ void finalize_kernel(float* __restrict__ out, int out_size) {
    int t = blockIdx.x * blockDim.x + threadIdx.x;
    if (t < N_PTS) {
        int o = ZQ_ELEMS + 3 + t;
        if (o < out_size) out[o] = (float)g_idx[t];
    }
    if (t == 0) {
        float mse  = g_acc * (1.0f / (float)ZQ_ELEMS);
        float comm = 0.25f * mse;
        if (ZQ_ELEMS + 0 < out_size) out[ZQ_ELEMS + 0] = __fadd_rn(comm, mse);
        if (ZQ_ELEMS + 1 < out_size) out[ZQ_ELEMS + 1] = comm;
        if (ZQ_ELEMS + 2 < out_size) out[ZQ_ELEMS + 2] = mse;
    }
}

extern "C" void kernel_launch(void* const* d_in, const int* in_sizes, int n_in,
                              void* d_out, int out_size) {
    const float* z = (const float*)d_in[0];
    const float* e = (const float*)d_in[1];
    float* out = (float*)d_out;
    cudaFuncSetAttribute(vq_main, cudaFuncAttributeMaxDynamicSharedMemorySize, SMEM_MAIN);
    prep_z_kernel<<<NTILES, 256>>>(z);
    prep_e_kernel<<<64, 256>>>(e);
    szT_kernel<<<1024, 256>>>(z);
    enorm_kernel<<<256, 256>>>(e);
    vq_main<<<1024, 256, SMEM_MAIN>>>();
    refine_kernel<<<4096, 256>>>(e);
    write_out_kernel<<<4096, 256>>>(z, e, out, out_size);
    finalize_kernel<<<(N_PTS + 255) / 256, 256>>>(out, out_size);
}

// round 6
// speedup vs baseline: 4.5126x; 1.4115x over previous
#include <cuda_runtime.h>
#include <cuda_fp16.h>
#include <cstdint>

#define N_PTS    32768
#define DIM      256
#define KCODES   8192
#define HW       1024
#define CHANS    256
#define ZQ_ELEMS (32 * 256 * 1024)

#define TM       128
#define NTILES   256
#define SB_STAGE 16384
#define SA_BYTES 65536
#define SMEM_MAIN (SA_BYTES + 4 * SB_STAGE)   // 131072
#define WO_SMEM  (128 * 257 * 4)              // 131584

typedef unsigned long long u64;

__device__ uint4 g_A4[NTILES * 4096];      // 16MB pre-swizzled z_hi fp16
__device__ uint4 g_B4[64 * 4 * 1024];      // 4MB  pre-swizzled e_hi fp16
__device__ float g_enorm[KCODES];
__device__ float g_sz[N_PTS];
__device__ float g_zT[N_PTS * DIM];        // contiguous z rows
__device__ u64   g_cand[N_PTS * 128];      // candidate pool
__device__ int   g_sel[N_PTS * 8];         // top-8 per point
__device__ int   g_idx[N_PTS];
__device__ float g_acc;

__device__ __forceinline__ uint32_t smem_u32(const void* p) {
    return (uint32_t)__cvta_generic_to_shared(p);
}
__device__ __forceinline__ void cpasync16(void* dst, const void* src) {
    asm volatile("cp.async.cg.shared.global [%0], [%1], 16;\n"
                 :: "r"(smem_u32(dst)), "l"(src));
}
#define CP_COMMIT() asm volatile("cp.async.commit_group;\n" ::: "memory")
#define CP_WAIT2()  asm volatile("cp.async.wait_group 2;\n" ::: "memory")

__device__ __forceinline__ void ldsm4(uint32_t* r, uint32_t addr) {
    asm volatile("ldmatrix.sync.aligned.m8n8.x4.shared.b16 {%0,%1,%2,%3}, [%4];"
                 : "=r"(r[0]), "=r"(r[1]), "=r"(r[2]), "=r"(r[3]) : "r"(addr));
}
__device__ __forceinline__ void mma16816(float* d, const uint32_t* a, const uint32_t* b) {
    asm volatile("mma.sync.aligned.m16n8k16.row.col.f32.f16.f16.f32 "
                 "{%0,%1,%2,%3}, {%4,%5,%6,%7}, {%8,%9}, {%0,%1,%2,%3};"
                 : "+f"(d[0]), "+f"(d[1]), "+f"(d[2]), "+f"(d[3])
                 : "r"(a[0]), "r"(a[1]), "r"(a[2]), "r"(a[3]), "r"(b[0]), "r"(b[1]));
}
__device__ __forceinline__ uint32_t pack2h(__half a, __half b) {
    return (uint32_t)__half_as_ushort(a) | ((uint32_t)__half_as_ushort(b) << 16);
}

// ---------- launch 1: prep A (pre-swizzled fp16 z_hi tiles) ----------
__global__ void prep_z_kernel(const float* __restrict__ z) {
    int t = blockIdx.x, tid = threadIdx.x;
    int n0 = t * TM, b = n0 >> 10, hw0 = n0 & 1023;
    const float* zb = z + (size_t)b * CHANS * HW + hw0;
    #pragma unroll
    for (int m = 0; m < 16; ++m) {
        int u = tid + m * 256;
        int p = u & 127, kc = u >> 7;
        __half h[8];
        #pragma unroll
        for (int j = 0; j < 8; ++j)
            h[j] = __float2half_rn(zb[(size_t)(kc * 8 + j) * HW + p]);
        uint4 hx = make_uint4(pack2h(h[0],h[1]), pack2h(h[2],h[3]),
                              pack2h(h[4],h[5]), pack2h(h[6],h[7]));
        int slot = p * 32 + ((kc & 24) | ((kc ^ (p & 7)) & 7));
        g_A4[(size_t)t * 4096 + slot] = hx;
    }
}

// ---------- launch 2: prep B (pre-swizzled fp16 e_hi slabs) ----------
__global__ void prep_e_kernel(const float* __restrict__ e) {
    int c = blockIdx.x, tid = threadIdx.x;
    #pragma unroll
    for (int m = 0; m < 16; ++m) {
        int u = tid + m * 256;
        int s = u >> 10;
        int w = u & 1023;
        int code = w >> 3, kc = w & 7;
        const float* ep = e + (size_t)(c * 128 + code) * DIM + s * 64 + kc * 8;
        __half h[8];
        #pragma unroll
        for (int j = 0; j < 8; ++j)
            h[j] = __float2half_rn(ep[j] * 8192.0f);
        uint4 x = make_uint4(pack2h(h[0],h[1]), pack2h(h[2],h[3]),
                             pack2h(h[4],h[5]), pack2h(h[6],h[7]));
        int slot = code * 8 + (kc ^ (code & 7));
        g_B4[((size_t)c * 4 + s) * 1024 + slot] = x;
    }
}

// ---------- launch 3: merged zT + ||z||^2 + ||e||^2 (+ zero acc) ----------
__global__ void szT_enorm_kernel(const float* __restrict__ z,
                                 const float* __restrict__ e) {
    int bid = blockIdx.x, tid = threadIdx.x;
    if (bid < 1024) {
        __shared__ float s_t[256 * 33];
        int n0 = bid * 32, b = n0 >> 10, hw0 = n0 & 1023;
        const float* zb = z + (size_t)b * CHANS * HW + hw0;
        #pragma unroll
        for (int m = 0; m < 32; ++m) {
            int c = m * 8 + (tid >> 5), p = tid & 31;
            s_t[c * 33 + p] = zb[(size_t)c * HW + p];
        }
        __syncthreads();
        if (tid < 32) {
            float s = 0.0f;
            #pragma unroll 8
            for (int c = 0; c < 256; ++c) {
                float v = s_t[c * 33 + tid];
                s = __fadd_rn(s, __fmul_rn(v, v));
            }
            g_sz[n0 + tid] = s;
        }
        #pragma unroll
        for (int m = 0; m < 8; ++m) {
            int p = tid >> 3, c0 = (tid & 7) * 4 + m * 32;
            float4 v;
            v.x = s_t[(c0    ) * 33 + p]; v.y = s_t[(c0 + 1) * 33 + p];
            v.z = s_t[(c0 + 2) * 33 + p]; v.w = s_t[(c0 + 3) * 33 + p];
            *(float4*)(g_zT + (size_t)(n0 + p) * DIM + c0) = v;
        }
    } else {
        int lane = tid & 31;
        int gw = (bid - 1024) * 8 + (tid >> 5);
        if (bid == 1024 && tid == 0) g_acc = 0.0f;
        #pragma unroll
        for (int i = 0; i < 4; ++i) {
            int k = gw * 4 + i;
            const float* row = e + (size_t)k * DIM + lane * 8;
            float s = 0.0f;
            #pragma unroll
            for (int j = 0; j < 8; ++j)
                s = __fadd_rn(s, __fmul_rn(row[j], row[j]));
            #pragma unroll
            for (int o = 16; o > 0; o >>= 1)
                s = __fadd_rn(s, __shfl_xor_sync(~0u, s, o));
            if (lane == 0) g_enorm[k] = s;
        }
    }
}

// ---------- launch 4: main approximate GEMM + top-2/thread candidates ----------
__global__ void __launch_bounds__(256, 1) vq_main() {
    extern __shared__ __align__(16) char sm[];
    char* sB = sm + SA_BYTES;
    const uint32_t sAu = smem_u32(sm);
    const uint32_t sBu = smem_u32(sB);

    const int tid = threadIdx.x;
    const int wid = tid >> 5, lane = tid & 31;
    const int wm = wid >> 2, wn = wid & 3;
    const int tile = blockIdx.x >> 2, q = blockIdx.x & 3;
    const int n0 = tile * TM;
    const uint4* Bbase = g_B4 + (size_t)q * 64 * 1024;

    {
        const uint4* Asrc = g_A4 + (size_t)tile * 4096;
        uint4* Adst = (uint4*)sm;
        #pragma unroll
        for (int m = 0; m < 16; ++m)
            cpasync16(Adst + tid + m * 256, Asrc + tid + m * 256);
        uint4* bd = (uint4*)sB;
        #pragma unroll
        for (int m = 0; m < 4; ++m) cpasync16(bd + tid + m * 256, Bbase + tid + m * 256);
        CP_COMMIT();
        #pragma unroll
        for (int m = 0; m < 4; ++m) cpasync16(bd + 1024 + tid + m * 256, Bbase + 1024 + tid + m * 256);
        CP_COMMIT();
        #pragma unroll
        for (int m = 0; m < 4; ++m) cpasync16(bd + 2048 + tid + m * 256, Bbase + 2048 + tid + m * 256);
        CP_COMMIT();
    }

    const int lrow = lane >> 2;
    const int lc2  = lane & 3;
    float szr[8];
    #pragma unroll
    for (int i = 0; i < 8; ++i) {
        int mi = i >> 1, h = i & 1;
        szr[i] = g_sz[n0 + wm * 64 + mi * 16 + lrow + h * 8];
    }
    float b1[8], b2[8];
    int   i1[8], i2[8];
    #pragma unroll
    for (int i = 0; i < 8; ++i) { b1[i] = 3.4e38f; b2[i] = 3.4e38f; i1[i] = 0; i2[i] = 0; }

    uint32_t aRow[4];
    int px7;
    {
        int p = (lane & 15);
        #pragma unroll
        for (int mi = 0; mi < 4; ++mi)
            aRow[mi] = (uint32_t)((wm * 64 + mi * 16 + p) * 512);
        px7 = (wm * 64 + p) & 7;
    }
    const int aCadd = (lane >> 4);
    int bCode[2], bKadd = (lane >> 3) & 1;
    bCode[0] = wn * 32 + (lane & 7) + ((lane >> 4) << 3);
    bCode[1] = bCode[0] + 16;

    float acc[4][4][4];

    for (int cg = 0; cg < 16; ++cg) {
        #pragma unroll
        for (int mi = 0; mi < 4; ++mi)
            #pragma unroll
            for (int nj = 0; nj < 4; ++nj)
                #pragma unroll
                for (int r = 0; r < 4; ++r) acc[mi][nj][r] = 0.0f;

        for (int s = 0; s < 4; ++s) {
            const int sidx = cg * 4 + s;
            CP_WAIT2();
            __syncthreads();
            const uint32_t bufb = sBu + (uint32_t)((sidx & 3) * SB_STAGE);

            #pragma unroll
            for (int js = 0; js < 4; ++js) {
                uint32_t bfr[8];
                {
                    int kc = js * 2 + bKadd;
                    ldsm4(bfr,     bufb + (uint32_t)(bCode[0] * 128 + ((kc ^ (bCode[0] & 7)) << 4)));
                    ldsm4(bfr + 4, bufb + (uint32_t)(bCode[1] * 128 + ((kc ^ (bCode[1] & 7)) << 4)));
                }
                const int c = s * 8 + js * 2 + aCadd;
                const uint32_t co = (uint32_t)(((c & 24) | ((c ^ px7) & 7)) << 4);
                uint32_t a[4][4];
                #pragma unroll
                for (int mi = 0; mi < 4; ++mi)
                    ldsm4(a[mi], sAu + aRow[mi] + co);
                #pragma unroll
                for (int mi = 0; mi < 4; ++mi) {
                    mma16816(acc[mi][0], a[mi], bfr);
                    mma16816(acc[mi][1], a[mi], bfr + 2);
                    mma16816(acc[mi][2], a[mi], bfr + 4);
                    mma16816(acc[mi][3], a[mi], bfr + 6);
                }
            }

            const int nx = sidx + 3;
            if (nx < 64) {
                const uint4* src = Bbase + (size_t)nx * 1024;
                uint4* dst = (uint4*)(sB + (nx & 3) * SB_STAGE);
                #pragma unroll
                for (int m = 0; m < 4; ++m)
                    cpasync16(dst + tid + m * 256, src + tid + m * 256);
            }
            CP_COMMIT();
        }

        // distances + per-thread top-2 (float compares; ties resolved in refine)
        const int cbase = q * 2048 + cg * 128 + wn * 32;
        float en[8];
        #pragma unroll
        for (int nj = 0; nj < 4; ++nj) {
            en[nj * 2]     = g_enorm[cbase + nj * 8 + lc2 * 2];
            en[nj * 2 + 1] = g_enorm[cbase + nj * 8 + lc2 * 2 + 1];
        }
        #pragma unroll
        for (int mi = 0; mi < 4; ++mi)
            #pragma unroll
            for (int nj = 0; nj < 4; ++nj)
                #pragma unroll
                for (int r = 0; r < 4; ++r) {
                    int i = mi * 2 + (r >> 1);
                    float t = __fmul_rn(acc[mi][nj][r], -2.44140625e-4f);
                    float d = __fadd_rn(__fadd_rn(szr[i], en[nj * 2 + (r & 1)]), t);
                    int idx = cbase + nj * 8 + lc2 * 2 + (r & 1);
                    if (d < b2[i]) {
                        if (d < b1[i]) { b2[i] = b1[i]; i2[i] = i1[i]; b1[i] = d; i1[i] = idx; }
                        else           { b2[i] = d; i2[i] = idx; }
                    }
                }
    }

    const int slot = (wn * 4 + lc2) * 2;
    #pragma unroll
    for (int i = 0; i < 8; ++i) {
        int mi = i >> 1, h = i & 1;
        int p = wm * 64 + mi * 16 + lrow + h * 8;
        u64* dst = g_cand + (size_t)(n0 + p) * 128 + q * 32 + slot;
        dst[0] = ((u64)__float_as_uint(b1[i]) << 32) | (unsigned)i1[i];
        dst[1] = ((u64)__float_as_uint(b2[i]) << 32) | (unsigned)i2[i];
    }
}

// ---------- launch 5: select top-8 of 128 candidates per point ----------
__global__ void select8_kernel() {
    int tid = threadIdx.x, lane = tid & 31;
    int p = blockIdx.x * 8 + (tid >> 5);
    u64 cand[4];
    #pragma unroll
    for (int j = 0; j < 4; ++j)
        cand[j] = g_cand[(size_t)p * 128 + lane * 4 + j];
    #pragma unroll 1
    for (int r = 0; r < 8; ++r) {
        u64 m = cand[0];
        if (cand[1] < m) m = cand[1];
        if (cand[2] < m) m = cand[2];
        if (cand[3] < m) m = cand[3];
        #pragma unroll
        for (int o = 16; o > 0; o >>= 1) {
            u64 w = __shfl_xor_sync(~0u, m, o);
            if (w < m) m = w;
        }
        #pragma unroll
        for (int j = 0; j < 4; ++j)
            if (cand[j] == m) cand[j] = ~0ULL;
        if (lane == 0) g_sel[p * 8 + r] = (int)(unsigned)m;
    }
}

// ---------- launch 6: parallel exact refine (block per point, warp per cand) ----------
__global__ void refine_dot_kernel(const float* __restrict__ e) {
    __shared__ u64 sres[8];
    int p = blockIdx.x, tid = threadIdx.x;
    int w = tid >> 5, lane = tid & 31;
    int k = g_sel[p * 8 + w];
    const float* zr = g_zT + (size_t)p * DIM + lane * 8;
    float4 za = *(const float4*)zr;
    float4 zb = *(const float4*)(zr + 4);
    const float* er = e + (size_t)k * DIM + lane * 8;
    float4 ea = *(const float4*)er;
    float4 eb = *(const float4*)(er + 4);
    float s = 0.0f;
    s = __fadd_rn(s, __fmul_rn(za.x, ea.x));
    s = __fadd_rn(s, __fmul_rn(za.y, ea.y));
    s = __fadd_rn(s, __fmul_rn(za.z, ea.z));
    s = __fadd_rn(s, __fmul_rn(za.w, ea.w));
    s = __fadd_rn(s, __fmul_rn(zb.x, eb.x));
    s = __fadd_rn(s, __fmul_rn(zb.y, eb.y));
    s = __fadd_rn(s, __fmul_rn(zb.z, eb.z));
    s = __fadd_rn(s, __fmul_rn(zb.w, eb.w));
    #pragma unroll
    for (int o = 16; o > 0; o >>= 1)
        s = __fadd_rn(s, __shfl_xor_sync(~0u, s, o));
    float d = __fadd_rn(__fadd_rn(g_sz[p], g_enorm[k]), __fmul_rn(s, -2.0f));
    if (lane == 0)
        sres[w] = ((u64)__float_as_uint(d) << 32) | (unsigned)k;
    __syncthreads();
    if (tid == 0) {
        u64 m = sres[0];
        #pragma unroll
        for (int j = 1; j < 8; ++j)
            if (sres[j] < m) m = sres[j];
        g_idx[p] = (int)(unsigned)m;
    }
}

// ---------- launch 7: z_q + MSE with smem-staged e rows ----------
__global__ void write_out2(const float* __restrict__ z,
                           const float* __restrict__ e,
                           float* __restrict__ out) {
    extern __shared__ float se[];            // [128][257]
    __shared__ int sidx[128];
    int blk = blockIdx.x, tid = threadIdx.x;
    int b = blk >> 3, hw0 = (blk & 7) * 128;
    if (tid < 128) sidx[tid] = g_idx[b * 1024 + hw0 + tid];
    __syncthreads();
    {
        int r = tid >> 1, half = tid & 1;
        const float* erow = e + (size_t)sidx[r] * DIM + half * 128;
        float* srow = se + r * 257 + half * 128;
        #pragma unroll
        for (int m = 0; m < 32; ++m) {
            float4 v = *(const float4*)(erow + m * 4);
            srow[m * 4]     = v.x; srow[m * 4 + 1] = v.y;
            srow[m * 4 + 2] = v.z; srow[m * 4 + 3] = v.w;
        }
    }
    __syncthreads();
    int p = tid & 127, ch = tid >> 7;
    const float* zb = z + (size_t)b * CHANS * HW + hw0 + p;
    float* ob = out + (size_t)b * CHANS * HW + hw0 + p;
    float local = 0.0f;
    #pragma unroll 4
    for (int it = 0; it < 128; ++it) {
        int c = it * 2 + ch;
        float zv = zb[(size_t)c * HW];
        float dq = __fsub_rn(se[p * 257 + c], zv);
        ob[(size_t)c * HW] = __fadd_rn(zv, dq);
        local = __fadd_rn(local, __fmul_rn(dq, dq));
    }
    #pragma unroll
    for (int o = 16; o > 0; o >>= 1) local += __shfl_xor_sync(~0u, local, o);
    __shared__ float ws[8];
    int lane = tid & 31, wd = tid >> 5;
    if (lane == 0) ws[wd] = local;
    __syncthreads();
    if (wd == 0) {
        float v = (lane < 8) ? ws[lane] : 0.0f;
        #pragma unroll
        for (int o = 4; o > 0; o >>= 1) v += __shfl_xor_sync(~0u, v, o);
        if (lane == 0) atomicAdd(&g_acc, v);
    }
}

// ---------- launch 8: scalars + indices ----------
__global__ void finalize_kernel(float* __restrict__ out, int out_size) {
    int t = blockIdx.x * blockDim.x + threadIdx.x;
    if (t < N_PTS) {
        int o = ZQ_ELEMS + 3 + t;
        if (o < out_size) out[o] = (float)g_idx[t];
    }
    if (t == 0) {
        float mse  = g_acc * (1.0f / (float)ZQ_ELEMS);
        float comm = 0.25f * mse;
        if (ZQ_ELEMS + 0 < out_size) out[ZQ_ELEMS + 0] = __fadd_rn(comm, mse);
        if (ZQ_ELEMS + 1 < out_size) out[ZQ_ELEMS + 1] = comm;
        if (ZQ_ELEMS + 2 < out_size) out[ZQ_ELEMS + 2] = mse;
    }
}

extern "C" void kernel_launch(void* const* d_in, const int* in_sizes, int n_in,
                              void* d_out, int out_size) {
    const float* z = (const float*)d_in[0];
    const float* e = (const float*)d_in[1];
    float* out = (float*)d_out;
    cudaFuncSetAttribute(vq_main, cudaFuncAttributeMaxDynamicSharedMemorySize, SMEM_MAIN);
    cudaFuncSetAttribute(write_out2, cudaFuncAttributeMaxDynamicSharedMemorySize, WO_SMEM);
    prep_z_kernel<<<NTILES, 256>>>(z);                 // 1
    prep_e_kernel<<<64, 256>>>(e);                     // 2
    szT_enorm_kernel<<<1280, 256>>>(z, e);             // 3
    vq_main<<<1024, 256, SMEM_MAIN>>>();               // 4  <- profiled launch
    select8_kernel<<<4096, 256>>>();                   // 5
    refine_dot_kernel<<<N_PTS, 256>>>(e);              // 6
    write_out2<<<256, 256, WO_SMEM>>>(z, e, out);      // 7
    finalize_kernel<<<(N_PTS + 255) / 256, 256>>>(out, out_size);  // 8
}